// round 2
// baseline (speedup 1.0000x reference)
#include <cuda_runtime.h>

#define NN 4096
#define DD 64
#define NITER 50
#define REGI 10.0f
#define INV_REG 0.1f
#define EPSF 1e-16f
#define AB (1.0f / 4096.0f)

// ---------------- persistent device state (no cudaMalloc allowed) ----------
__device__ float g_E[(size_t)NN * NN];   // exp(-M/reg), 64 MiB — lives in L2
__device__ float g_xs[NN], g_ys[NN];     // squared norms
__device__ float g_su[NN], g_sv[NN];     // invariant scalings ea*u, eb*v
__device__ float g_part[128];            // per-block loss partials

// ---------------- squared norms + state init -------------------------------
__global__ __launch_bounds__(256) void k_norms(const float* __restrict__ x,
                                               const float* __restrict__ y) {
    int i = blockIdx.x * blockDim.x + threadIdx.x;
    if (i < NN) {
        const float4* p = (const float4*)(x + (size_t)i * DD);
        float s = 0.f;
#pragma unroll
        for (int d = 0; d < DD / 4; d++) {
            float4 v = p[d];
            s += v.x * v.x + v.y * v.y + v.z * v.z + v.w * v.w;
        }
        g_xs[i] = s;
        g_su[i] = AB;               // initial u = a, alpha = 0
    } else if (i < 2 * NN) {
        int j = i - NN;
        const float4* p = (const float4*)(y + (size_t)j * DD);
        float s = 0.f;
#pragma unroll
        for (int d = 0; d < DD / 4; d++) {
            float4 v = p[d];
            s += v.x * v.x + v.y * v.y + v.z * v.z + v.w * v.w;
        }
        g_ys[j] = s;
    }
}

// ---------------- E = exp(-M/reg), tiled 64x64 GEMM-like -------------------
// M_ij = xs_i + ys_j - 2 * <x_i, y_j>
__global__ __launch_bounds__(256) void k_buildE(const float* __restrict__ x,
                                                const float* __restrict__ y) {
    __shared__ float Xs[DD][68];   // transposed: Xs[k][r], padded for LDS.128
    __shared__ float Ys[DD][68];
    const int i0 = blockIdx.y * 64;
    const int j0 = blockIdx.x * 64;
    const int tid = threadIdx.x;

    for (int idx = tid; idx < 64 * 64; idx += 256) {
        int r = idx >> 6, k = idx & 63;
        Xs[k][r] = x[(size_t)(i0 + r) * DD + k];
        Ys[k][r] = y[(size_t)(j0 + r) * DD + k];
    }
    __syncthreads();

    const int tx = tid & 15;      // 16 col-groups of 4
    const int ty = tid >> 4;      // 16 row-groups of 4
    float acc[4][4] = {};

#pragma unroll
    for (int k = 0; k < DD; k++) {
        float4 av = *(const float4*)&Xs[k][ty * 4];
        float4 bv = *(const float4*)&Ys[k][tx * 4];
        float ar[4] = {av.x, av.y, av.z, av.w};
        float br[4] = {bv.x, bv.y, bv.z, bv.w};
#pragma unroll
        for (int r = 0; r < 4; r++)
#pragma unroll
            for (int c = 0; c < 4; c++)
                acc[r][c] += ar[r] * br[c];
    }

    float xr[4], yc[4];
#pragma unroll
    for (int r = 0; r < 4; r++) xr[r] = g_xs[i0 + ty * 4 + r];
#pragma unroll
    for (int c = 0; c < 4; c++) yc[c] = g_ys[j0 + tx * 4 + c];

#pragma unroll
    for (int r = 0; r < 4; r++) {
        float4 o;
        o.x = __expf((2.f * acc[r][0] - xr[r] - yc[0]) * INV_REG);
        o.y = __expf((2.f * acc[r][1] - xr[r] - yc[1]) * INV_REG);
        o.z = __expf((2.f * acc[r][2] - xr[r] - yc[2]) * INV_REG);
        o.w = __expf((2.f * acc[r][3] - xr[r] - yc[3]) * INV_REG);
        *(float4*)&g_E[(size_t)(i0 + ty * 4 + r) * NN + j0 + tx * 4] = o;
    }
}

// ---------------- column pass: sv_j = b / (sum_i E_ij * su_i + eps) --------
// grid 128 blocks x 256 thr; block owns 32 columns; 8 warps split rows.
__global__ __launch_bounds__(256) void k_col() {
    __shared__ float ssu[NN];          // 16 KB
    __shared__ float red[8][32];
    const int tid = threadIdx.x;
    for (int idx = tid; idx < NN; idx += 256) ssu[idx] = g_su[idx];
    __syncthreads();

    const int l = tid & 31;
    const int w = tid >> 5;
    const int c = blockIdx.x * 32 + l;
    const float* __restrict__ p = g_E + (size_t)(w * 512) * NN + c;
    const float* __restrict__ su = ssu + w * 512;
    float acc = 0.f;
#pragma unroll 8
    for (int r = 0; r < 512; r++) {
        acc += p[0] * su[r];
        p += NN;
    }
    red[w][l] = acc;
    __syncthreads();
    if (w == 0) {
        float s = 0.f;
#pragma unroll
        for (int q = 0; q < 8; q++) s += red[q][tid];
        g_sv[blockIdx.x * 32 + tid] = AB / (s + EPSF);
    }
}

// ---------------- row pass: su_i = a / (sum_j E_ij * sv_j + eps) -----------
// grid 128 blocks x 256 thr; block owns 32 rows; warp-per-row, 4 groups.
__global__ __launch_bounds__(256) void k_row() {
    __shared__ float ssv[NN];          // 16 KB
    const int tid = threadIdx.x;
    for (int idx = tid; idx < NN; idx += 256) ssv[idx] = g_sv[idx];
    __syncthreads();

    const int w = tid >> 5, l = tid & 31;
#pragma unroll 1
    for (int g = 0; g < 4; g++) {
        const int row = blockIdx.x * 32 + g * 8 + w;
        const float4* __restrict__ e4 = (const float4*)(g_E + (size_t)row * NN);
        float acc = 0.f;
#pragma unroll 8
        for (int q = 0; q < 32; q++) {
            float4 e = e4[q * 32 + l];
            float4 s = *(const float4*)&ssv[(q * 32 + l) * 4];
            acc += e.x * s.x + e.y * s.y + e.z * s.z + e.w * s.w;
        }
#pragma unroll
        for (int o = 16; o; o >>= 1) acc += __shfl_xor_sync(~0u, acc, o);
        if (l == 0) g_su[row] = AB / (acc + EPSF);
    }
}

// ---------------- loss: sum_ij E*M*su*sv, M = -reg*ln(E) -------------------
__global__ __launch_bounds__(256) void k_loss() {
    __shared__ float ssv[NN];
    __shared__ float wsum[8];
    const int tid = threadIdx.x;
    for (int idx = tid; idx < NN; idx += 256) ssv[idx] = g_sv[idx];
    __syncthreads();

    const int w = tid >> 5, l = tid & 31;
    float wacc = 0.f;
#pragma unroll 1
    for (int g = 0; g < 4; g++) {
        const int row = blockIdx.x * 32 + g * 8 + w;
        const float4* __restrict__ e4 = (const float4*)(g_E + (size_t)row * NN);
        float acc = 0.f;
        for (int q = 0; q < 32; q++) {
            float4 e = e4[q * 32 + l];
            float4 s = *(const float4*)&ssv[(q * 32 + l) * 4];
            acc += e.x * __logf(e.x) * s.x + e.y * __logf(e.y) * s.y +
                   e.z * __logf(e.z) * s.z + e.w * __logf(e.w) * s.w;
        }
#pragma unroll
        for (int o = 16; o; o >>= 1) acc += __shfl_xor_sync(~0u, acc, o);
        if (l == 0) wacc += acc * g_su[row];
    }
    if (l == 0) wsum[w] = wacc;
    __syncthreads();
    if (tid == 0) {
        float s = 0.f;
#pragma unroll
        for (int q = 0; q < 8; q++) s += wsum[q];
        g_part[blockIdx.x] = -REGI * s;   // E*M = -reg * E*ln(E)
    }
}

__global__ __launch_bounds__(128) void k_final(float* __restrict__ out) {
    const int t = threadIdx.x;
    float v = g_part[t];
#pragma unroll
    for (int o = 16; o; o >>= 1) v += __shfl_xor_sync(~0u, v, o);
    __shared__ float ws[4];
    if ((t & 31) == 0) ws[t >> 5] = v;
    __syncthreads();
    if (t == 0) out[0] = ws[0] + ws[1] + ws[2] + ws[3];
}

// ---------------------------------------------------------------------------
extern "C" void kernel_launch(void* const* d_in, const int* in_sizes, int n_in,
                              void* d_out, int out_size) {
    const float* x = (const float*)d_in[0];
    const float* y = (const float*)d_in[1];
    float* out = (float*)d_out;

    k_norms<<<32, 256>>>(x, y);
    dim3 eg(64, 64);
    k_buildE<<<eg, 256>>>(x, y);
    for (int it = 0; it < NITER; it++) {
        k_col<<<128, 256>>>();
        k_row<<<128, 256>>>();
    }
    k_loss<<<128, 256>>>();
    k_final<<<1, 128>>>(out);
}

// round 3
// speedup vs baseline: 2.6685x; 2.6685x over previous
#include <cuda_runtime.h>
#include <cuda_fp16.h>

#define NN 4096
#define DD 64
#define NITER 50
#define REGI 10.0f
#define INV_REG 0.1f
#define EPSF 1e-16f
#define AB (1.0f / 4096.0f)

#define SCALE 262144.0f          // 2^18
#define INV_SCALE (1.0f / 262144.0f)
#define LN_SCALE 12.476649250079f // 18*ln2

// ---------------- persistent device state (no cudaMalloc allowed) ----------
__device__ uint4 g_E4[(size_t)NN * NN / 8];   // Ê = exp(-M/reg)*2^18 in fp16, 32 MiB
__device__ float g_xs[NN], g_ys[NN];
__device__ float g_cp[8][NN];    // column-sum partials (8 row-chunks)
__device__ float g_rp[4][NN];    // row-sum partials (4 col-chunks)
__device__ float g_part[512];

// ---------------- norms + initial row-partials (su == a) -------------------
__global__ __launch_bounds__(256) void k_norms(const float* __restrict__ x,
                                               const float* __restrict__ y) {
    int i = blockIdx.x * blockDim.x + threadIdx.x;
    if (i < NN) {
        const float4* p = (const float4*)(x + (size_t)i * DD);
        float s = 0.f;
#pragma unroll
        for (int d = 0; d < DD / 4; d++) {
            float4 v = p[d];
            s += v.x * v.x + v.y * v.y + v.z * v.z + v.w * v.w;
        }
        g_xs[i] = s;
    } else if (i < 2 * NN) {
        int j = i - NN;
        const float4* p = (const float4*)(y + (size_t)j * DD);
        float s = 0.f;
#pragma unroll
        for (int d = 0; d < DD / 4; d++) {
            float4 v = p[d];
            s += v.x * v.x + v.y * v.y + v.z * v.z + v.w * v.w;
        }
        g_ys[j] = s;
    } else if (i < 6 * NN) {
        int idx = i - 2 * NN;
        int q = idx >> 12, r = idx & (NN - 1);
        g_rp[q][r] = (q == 0) ? SCALE : 0.f;   // => su = AB/(1+eps) = a
    }
}

// ---------------- Ê = exp(-M/reg)*2^18 as fp16 -----------------------------
__global__ __launch_bounds__(256) void k_buildE(const float* __restrict__ x,
                                                const float* __restrict__ y) {
    __shared__ float Xs[DD][68];
    __shared__ float Ys[DD][68];
    const int i0 = blockIdx.y * 64;
    const int j0 = blockIdx.x * 64;
    const int tid = threadIdx.x;

    for (int idx = tid; idx < 64 * 64; idx += 256) {
        int r = idx >> 6, k = idx & 63;
        Xs[k][r] = x[(size_t)(i0 + r) * DD + k];
        Ys[k][r] = y[(size_t)(j0 + r) * DD + k];
    }
    __syncthreads();

    const int tx = tid & 15;
    const int ty = tid >> 4;
    float acc[4][4] = {};

#pragma unroll
    for (int k = 0; k < DD; k++) {
        float4 av = *(const float4*)&Xs[k][ty * 4];
        float4 bv = *(const float4*)&Ys[k][tx * 4];
        float ar[4] = {av.x, av.y, av.z, av.w};
        float br[4] = {bv.x, bv.y, bv.z, bv.w};
#pragma unroll
        for (int r = 0; r < 4; r++)
#pragma unroll
            for (int c = 0; c < 4; c++)
                acc[r][c] += ar[r] * br[c];
    }

    float xr[4], yc[4];
#pragma unroll
    for (int r = 0; r < 4; r++) xr[r] = g_xs[i0 + ty * 4 + r];
#pragma unroll
    for (int c = 0; c < 4; c++) yc[c] = g_ys[j0 + tx * 4 + c];

    __half* Eh = (__half*)g_E4;
#pragma unroll
    for (int r = 0; r < 4; r++) {
        float e0 = __expf((2.f * acc[r][0] - xr[r] - yc[0]) * INV_REG + LN_SCALE);
        float e1 = __expf((2.f * acc[r][1] - xr[r] - yc[1]) * INV_REG + LN_SCALE);
        float e2 = __expf((2.f * acc[r][2] - xr[r] - yc[2]) * INV_REG + LN_SCALE);
        float e3 = __expf((2.f * acc[r][3] - xr[r] - yc[3]) * INV_REG + LN_SCALE);
        union { uint2 u; __half2 h[2]; } pk;
        pk.h[0] = __floats2half2_rn(e0, e1);
        pk.h[1] = __floats2half2_rn(e2, e3);
        *(uint2*)(Eh + (size_t)(i0 + ty * 4 + r) * NN + j0 + tx * 4) = pk.u;
    }
}

// ---------------- column pass ----------------------------------------------
// grid (64, 8): block = 64 cols x 512 rows. Finalizes su from rp in preamble.
// Writes cp[by][64 cols].
__global__ __launch_bounds__(256) void k_col() {
    __shared__ float ssu[512];
    __shared__ float2 sred[8][32];
    const int tid = threadIdx.x;
    const int bx = blockIdx.x, by = blockIdx.y;
    const int r0 = by * 512;

    for (int i = tid; i < 512; i += 256) {
        int r = r0 + i;
        float s = g_rp[0][r] + g_rp[1][r] + g_rp[2][r] + g_rp[3][r];
        ssu[i] = AB / (s * INV_SCALE + EPSF);
    }
    __syncthreads();

    const int w = tid >> 5, l = tid & 31;
    const __half2* p = (const __half2*)g_E4 +
                       (size_t)(r0 + w * 64) * (NN / 2) + bx * 32 + l;
    const float* su = ssu + w * 64;
    float2 acc = {0.f, 0.f};
#pragma unroll 8
    for (int r = 0; r < 64; r++) {
        float2 e = __half22float2(p[(size_t)r * (NN / 2)]);
        float s = su[r];
        acc.x += e.x * s;
        acc.y += e.y * s;
    }
    sred[w][l] = acc;
    __syncthreads();
    if (w == 0) {
        float2 s = {0.f, 0.f};
#pragma unroll
        for (int q = 0; q < 8; q++) { s.x += sred[q][l].x; s.y += sred[q][l].y; }
        g_cp[by][bx * 64 + 2 * l]     = s.x;
        g_cp[by][bx * 64 + 2 * l + 1] = s.y;
    }
}

// ---------------- row pass -------------------------------------------------
// grid (128, 4): block = 32 rows x 1024 cols. Finalizes sv from cp in
// preamble (stored as fp16 pairs in smem — conflict-free). Writes rp[by][rows].
__global__ __launch_bounds__(256) void k_row() {
    __shared__ __half2 ssv[512];
    const int tid = threadIdx.x;
    const int bx = blockIdx.x, by = blockIdx.y;
    const int c0 = by * 1024;

    for (int i = tid; i < 512; i += 256) {
        int c = c0 + 2 * i;
        float s0 = 0.f, s1 = 0.f;
#pragma unroll
        for (int q = 0; q < 8; q++) { s0 += g_cp[q][c]; s1 += g_cp[q][c + 1]; }
        float v0 = AB / (s0 * INV_SCALE + EPSF);
        float v1 = AB / (s1 * INV_SCALE + EPSF);
        ssv[i] = __floats2half2_rn(v0, v1);
    }
    __syncthreads();

    const int w = tid >> 5, l = tid & 31;
#pragma unroll
    for (int rr = 0; rr < 4; rr++) {
        const int row = bx * 32 + w * 4 + rr;
        const uint4* e4 = g_E4 + (size_t)row * (NN / 8) + by * 128 + l;
        const uint4* sp = (const uint4*)ssv + l;   // 8 halves per lane
        float acc = 0.f;
#pragma unroll
        for (int st = 0; st < 4; st++) {
            uint4 ev = e4[st * 32];
            uint4 vv = sp[st * 32];
            const __half2* eh = (const __half2*)&ev;
            const __half2* vh = (const __half2*)&vv;
#pragma unroll
            for (int k = 0; k < 4; k++) {
                float2 e = __half22float2(eh[k]);
                float2 v = __half22float2(vh[k]);
                acc += e.x * v.x + e.y * v.y;
            }
        }
#pragma unroll
        for (int o = 16; o; o >>= 1) acc += __shfl_xor_sync(~0u, acc, o);
        if (l == 0) g_rp[by][row] = acc;
    }
}

// ---------------- loss -----------------------------------------------------
// loss = reg * invS * sum_ij su_i * sv_j * Ê_ij * (lnS - ln Ê_ij)
__global__ __launch_bounds__(256) void k_loss() {
    __shared__ __half2 ssv[512];
    __shared__ float ssu[32];
    __shared__ float wred[8];
    const int tid = threadIdx.x;
    const int bx = blockIdx.x, by = blockIdx.y;
    const int c0 = by * 1024;

    for (int i = tid; i < 512; i += 256) {
        int c = c0 + 2 * i;
        float s0 = 0.f, s1 = 0.f;
#pragma unroll
        for (int q = 0; q < 8; q++) { s0 += g_cp[q][c]; s1 += g_cp[q][c + 1]; }
        float v0 = AB / (s0 * INV_SCALE + EPSF);
        float v1 = AB / (s1 * INV_SCALE + EPSF);
        ssv[i] = __floats2half2_rn(v0, v1);
    }
    if (tid < 32) {
        int r = bx * 32 + tid;
        float s = g_rp[0][r] + g_rp[1][r] + g_rp[2][r] + g_rp[3][r];
        ssu[tid] = AB / (s * INV_SCALE + EPSF);
    }
    __syncthreads();

    const int w = tid >> 5, l = tid & 31;
    float wacc = 0.f;
#pragma unroll 1
    for (int rr = 0; rr < 4; rr++) {
        const int row = bx * 32 + w * 4 + rr;
        const uint4* e4 = g_E4 + (size_t)row * (NN / 8) + by * 128 + l;
        const uint4* sp = (const uint4*)ssv + l;
        float acc = 0.f;
#pragma unroll
        for (int st = 0; st < 4; st++) {
            uint4 ev = e4[st * 32];
            uint4 vv = sp[st * 32];
            const __half2* eh = (const __half2*)&ev;
            const __half2* vh = (const __half2*)&vv;
#pragma unroll
            for (int k = 0; k < 4; k++) {
                float2 e = __half22float2(eh[k]);
                float2 v = __half22float2(vh[k]);
                float t0 = (e.x > 0.f) ? e.x * (LN_SCALE - __logf(e.x)) : 0.f;
                float t1 = (e.y > 0.f) ? e.y * (LN_SCALE - __logf(e.y)) : 0.f;
                acc += t0 * v.x + t1 * v.y;
            }
        }
#pragma unroll
        for (int o = 16; o; o >>= 1) acc += __shfl_xor_sync(~0u, acc, o);
        if (l == 0) wacc += ssu[w * 4 + rr] * acc;
    }
    if (l == 0) wred[w] = wacc;
    __syncthreads();
    if (tid == 0) {
        float s = 0.f;
#pragma unroll
        for (int q = 0; q < 8; q++) s += wred[q];
        g_part[bx * 4 + by] = REGI * INV_SCALE * s;
    }
}

__global__ __launch_bounds__(512) void k_final(float* __restrict__ out) {
    const int t = threadIdx.x;
    float v = g_part[t];
#pragma unroll
    for (int o = 16; o; o >>= 1) v += __shfl_xor_sync(~0u, v, o);
    __shared__ float ws[16];
    if ((t & 31) == 0) ws[t >> 5] = v;
    __syncthreads();
    if (t < 32) {
        float s = (t < 16) ? ws[t] : 0.f;
#pragma unroll
        for (int o = 8; o; o >>= 1) s += __shfl_xor_sync(~0u, s, o);
        if (t == 0) out[0] = s;
    }
}

// ---------------------------------------------------------------------------
extern "C" void kernel_launch(void* const* d_in, const int* in_sizes, int n_in,
                              void* d_out, int out_size) {
    const float* x = (const float*)d_in[0];
    const float* y = (const float*)d_in[1];
    float* out = (float*)d_out;

    k_norms<<<96, 256>>>(x, y);
    k_buildE<<<dim3(64, 64), 256>>>(x, y);
    for (int it = 0; it < NITER; it++) {
        k_col<<<dim3(64, 8), 256>>>();
        k_row<<<dim3(128, 4), 256>>>();
    }
    k_loss<<<dim3(128, 4), 256>>>();
    k_final<<<1, 512>>>(out);
}